// round 5
// baseline (speedup 1.0000x reference)
#include <cuda_runtime.h>
#include <math.h>

// Fixed problem shapes
#define Bv   16
#define Cc   256
#define Nn   64
#define NN   4096
#define Ss   128
#define EPSN 1e-12f
#define SCALE 10.0f
#define TPB  512     // 8 teams x 64 threads

typedef unsigned long long ull;

// Scratch: normalized sentence features + offsets
__device__ float g_sn1[Ss * Cc];
__device__ float g_sn2[Ss * Cc];
__device__ int   g_off[Bv + 1];

// Packed dual-fp32 FMA / ADD (Blackwell)
#define FFMA2(acc, a, bb) \
    asm("fma.rn.f32x2 %0, %1, %2, %0;" : "+l"(acc) : "l"(a), "l"(bb))
#define FADD2(dst, a, bb) \
    asm("add.rn.f32x2 %0, %1, %2;" : "=l"(dst) : "l"(a), "l"(bb))

__device__ __forceinline__ float f2lo(ull x) {
    return __uint_as_float((unsigned)(x & 0xffffffffu));
}
__device__ __forceinline__ float f2hi(ull x) {
    return __uint_as_float((unsigned)(x >> 32));
}

// ---------------------------------------------------------------------------
// Kernel 1: normalize sentence features (warp per row) + prefix offsets
// ---------------------------------------------------------------------------
__global__ void prep_kernel(const float* __restrict__ sf1,
                            const float* __restrict__ sf2,
                            const int*   __restrict__ nums) {
    if (blockIdx.x == 0 && threadIdx.x == 0) {
        int acc = 0;
        g_off[0] = 0;
        #pragma unroll
        for (int i = 0; i < Bv; i++) { acc += nums[i]; g_off[i + 1] = acc; }
    }
    int warp = threadIdx.x >> 5;
    int lane = threadIdx.x & 31;
    int row  = blockIdx.x * 8 + warp;   // 2S rows
    const float* src;
    float* dst;
    if (row < Ss) { src = sf1 + (size_t)row * Cc;        dst = g_sn1 + (size_t)row * Cc; }
    else          { src = sf2 + (size_t)(row - Ss) * Cc; dst = g_sn2 + (size_t)(row - Ss) * Cc; }

    float v[8];
    float sum = 0.f;
    #pragma unroll
    for (int k = 0; k < 8; k++) {
        v[k] = src[lane + 32 * k];
        sum += v[k] * v[k];
    }
    #pragma unroll
    for (int o = 16; o; o >>= 1) sum += __shfl_xor_sync(0xffffffffu, sum, o);
    float inv = 1.f / fmaxf(sqrtf(sum), EPSN);
    #pragma unroll
    for (int k = 0; k < 8; k++) dst[lane + 32 * k] = v[k] * inv;
}

// ---------------------------------------------------------------------------
// Kernel 2: fused dual-space scoring.
// Block = 512 thr = 8 teams x 64. team = (space sp, channel-quarter q).
// Thread owns 2 adjacent columns (LDG.64 per channel), 8 sentences, 64
// channels -> small accumulator payload allows 3 blocks/SM (~75% occ).
// Video feats read exactly once from HBM. One 32 KB smem buffer aliased
// between the sentence stage and the reduction scratch (barrier-separated).
// Partials reduced via a 3-level tree; team (0,0) runs the fused epilogue.
// grid = (4096/128, Bv) = (32,16) = 512 blocks.
// ---------------------------------------------------------------------------
__global__ __launch_bounds__(TPB, 3) void score_kernel(
    const float* __restrict__ vf1,
    const float* __restrict__ vf2,
    const float* __restrict__ mask2d,
    float* __restrict__ out) {

    // 32 KB, two phase-disjoint uses:
    //  - stage: duplicated sentence pairs, idx (spp*256+c)*8+s  (4096 ull)
    //  - reduce: 256 slots x 9 ull (max idx 2303)
    __shared__ ull buf[4096];

    const int tid  = threadIdx.x;
    const int team = tid >> 6;       // 0..7
    const int ttid = tid & 63;
    const int sp   = team >> 2;      // feature space
    const int q    = team & 3;       // channel quarter
    const int b    = blockIdx.y;
    const int ij0  = blockIdx.x * 128 + 2 * ttid;

    const int start = g_off[b];
    int end = g_off[b + 1];
    if (end > Ss) end = Ss;
    if (start >= end) return;        // uniform per block

    const float* vf = (sp == 0) ? vf1 : vf2;
    const ull* __restrict__ v = reinterpret_cast<const ull*>(
        vf + ((size_t)b * Cc + (size_t)q * 64) * NN + ij0);

    const ull* __restrict__ sb = buf + (size_t)(sp * 256 + q * 64) * 8;

    for (int cs = start; cs < end; cs += 8) {
        const int cnt = min(8, end - cs);

        // Stage duplicated sentence scalars (all 512 threads, 4096 ull)
        for (int e = tid; e < 2 * Cc * 8; e += TPB) {
            const int s   = e & 7;
            const int c   = (e >> 3) & (Cc - 1);
            const int spp = e >> 11;
            float val = 0.f;
            if (s < cnt)
                val = (spp == 0 ? g_sn1 : g_sn2)[(size_t)(cs + s) * Cc + c];
            float2 d = make_float2(val, val);
            buf[e] = *reinterpret_cast<ull*>(&d);
        }
        __syncthreads();

        ull acc[8];
        #pragma unroll
        for (int s = 0; s < 8; s++) acc[s] = 0ull;
        ull nrm = 0ull;

        #pragma unroll 4
        for (int k = 0; k < 64; k++) {
            const ull a = v[(size_t)k * (NN / 2)];
            FFMA2(nrm, a, a);
            const ulonglong2* p =
                reinterpret_cast<const ulonglong2*>(sb + k * 8);
            const ulonglong2 q0 = p[0];
            const ulonglong2 q1 = p[1];
            FFMA2(acc[0], a, q0.x); FFMA2(acc[1], a, q0.y);
            FFMA2(acc[2], a, q1.x); FFMA2(acc[3], a, q1.y);
            const ulonglong2 q2 = p[2];
            const ulonglong2 q3 = p[3];
            FFMA2(acc[4], a, q2.x); FFMA2(acc[5], a, q2.y);
            FFMA2(acc[6], a, q3.x); FFMA2(acc[7], a, q3.y);
        }
        __syncthreads();   // stage reads done; buf now reduction scratch

        // ---- Reduction tree over channel quarters ----
        // L1: quarters 2,3 publish (slots 0..255); quarters 0,1 add
        if (q >= 2) {
            ull* w = buf + ((size_t)((sp * 2 + (q - 2)) * 64 + ttid)) * 9;
            #pragma unroll
            for (int s = 0; s < 8; s++) w[s] = acc[s];
            w[8] = nrm;
        }
        __syncthreads();
        if (q < 2) {
            const ull* r = buf + ((size_t)((sp * 2 + q) * 64 + ttid)) * 9;
            #pragma unroll
            for (int s = 0; s < 8; s++) FADD2(acc[s], acc[s], r[s]);
            FADD2(nrm, nrm, r[8]);
        }
        __syncthreads();
        // L2: quarter 1 publishes half-sums (slots 0..127); quarter 0 adds
        if (q == 1) {
            ull* w = buf + ((size_t)(sp * 64 + ttid)) * 9;
            #pragma unroll
            for (int s = 0; s < 8; s++) w[s] = acc[s];
            w[8] = nrm;
        }
        __syncthreads();
        if (q == 0) {
            const ull* r = buf + ((size_t)(sp * 64 + ttid)) * 9;
            #pragma unroll
            for (int s = 0; s < 8; s++) FADD2(acc[s], acc[s], r[s]);
            FADD2(nrm, nrm, r[8]);
        }
        __syncthreads();
        // L3: space-2 full sums -> slots 128..191
        if (q == 0 && sp == 1) {
            ull* w = buf + ((size_t)(128 + ttid)) * 9;
            #pragma unroll
            for (int s = 0; s < 8; s++) w[s] = acc[s];
            w[8] = nrm;
        }
        __syncthreads();

        // ---- Fused epilogue: team (0,0) only ----
        if (team == 0) {
            const ull* r2 = buf + ((size_t)(128 + ttid)) * 9;

            const float i1lo = 1.f / fmaxf(sqrtf(f2lo(nrm)), EPSN);
            const float i1hi = 1.f / fmaxf(sqrtf(f2hi(nrm)), EPSN);
            const ull n2 = r2[8];
            const float i2lo = 1.f / fmaxf(sqrtf(f2lo(n2)), EPSN);
            const float i2hi = 1.f / fmaxf(sqrtf(f2hi(n2)), EPSN);

            const float2 mv = *reinterpret_cast<const float2*>(mask2d + ij0);
            const float m0 = mv.x, m1 = mv.y;

            for (int s = 0; s < cnt; s++) {
                const size_t srow = (size_t)(cs + s);
                const float lglo = SCALE * (f2lo(acc[s]) * i1lo);
                const float lghi = SCALE * (f2hi(acc[s]) * i1hi);
                *reinterpret_cast<float2*>(out + srow * NN + ij0) =
                    make_float2(lglo, lghi);

                const float ioulo = m0 / (1.f + __expf(-lglo));
                const float iouhi = m1 / (1.f + __expf(-lghi));
                const float conlo =
                    fmaxf((f2lo(r2[s]) * i2lo + 1.f) * 0.5f * m0, 0.f);
                const float conhi =
                    fmaxf((f2hi(r2[s]) * i2hi + 1.f) * 0.5f * m1, 0.f);
                *reinterpret_cast<float2*>(
                    out + (size_t)Ss * NN + srow * NN + ij0) =
                    make_float2(sqrtf(conlo) * ioulo, sqrtf(conhi) * iouhi);
            }
        }
        __syncthreads();   // buf safe to restage
    }
}

// ---------------------------------------------------------------------------
extern "C" void kernel_launch(void* const* d_in, const int* in_sizes, int n_in,
                              void* d_out, int out_size) {
    const float* vf1  = (const float*)d_in[0];
    const float* vf2  = (const float*)d_in[1];
    const float* sf1  = (const float*)d_in[2];
    const float* sf2  = (const float*)d_in[3];
    const float* mask = (const float*)d_in[4];
    const int*   nums = (const int*)d_in[5];
    float* out = (float*)d_out;

    prep_kernel<<<(2 * Ss) / 8, 256>>>(sf1, sf2, nums);
    score_kernel<<<dim3(NN / 128, Bv), TPB>>>(vf1, vf2, mask, out);
}

// round 7
// speedup vs baseline: 1.3458x; 1.3458x over previous
#include <cuda_runtime.h>
#include <math.h>

// Fixed problem shapes
#define Bv   16
#define Cc   256
#define Nn   64
#define NN   4096
#define Ss   128
#define EPSN 1e-12f
#define SCALE 10.0f
#define TPB  512     // 4 teams x 128 threads

typedef unsigned long long ull;

// Scratch: normalized sentence features + offsets
__device__ float g_sn1[Ss * Cc];
__device__ float g_sn2[Ss * Cc];
__device__ int   g_off[Bv + 1];

// Packed dual-fp32 FMA / ADD (Blackwell)
#define FFMA2(acc, a, bb) \
    asm("fma.rn.f32x2 %0, %1, %2, %0;" : "+l"(acc) : "l"(a), "l"(bb))
#define FADD2(dst, a, bb) \
    asm("add.rn.f32x2 %0, %1, %2;" : "=l"(dst) : "l"(a), "l"(bb))

__device__ __forceinline__ float f2lo(ull x) {
    return __uint_as_float((unsigned)(x & 0xffffffffu));
}
__device__ __forceinline__ float f2hi(ull x) {
    return __uint_as_float((unsigned)(x >> 32));
}

// ---------------------------------------------------------------------------
// Kernel 1: normalize sentence features (warp per row) + prefix offsets
// ---------------------------------------------------------------------------
__global__ void prep_kernel(const float* __restrict__ sf1,
                            const float* __restrict__ sf2,
                            const int*   __restrict__ nums) {
    if (blockIdx.x == 0 && threadIdx.x == 0) {
        int acc = 0;
        g_off[0] = 0;
        #pragma unroll
        for (int i = 0; i < Bv; i++) { acc += nums[i]; g_off[i + 1] = acc; }
    }
    int warp = threadIdx.x >> 5;
    int lane = threadIdx.x & 31;
    int row  = blockIdx.x * 8 + warp;   // 2S rows
    const float* src;
    float* dst;
    if (row < Ss) { src = sf1 + (size_t)row * Cc;        dst = g_sn1 + (size_t)row * Cc; }
    else          { src = sf2 + (size_t)(row - Ss) * Cc; dst = g_sn2 + (size_t)(row - Ss) * Cc; }

    float v[8];
    float sum = 0.f;
    #pragma unroll
    for (int k = 0; k < 8; k++) {
        v[k] = src[lane + 32 * k];
        sum += v[k] * v[k];
    }
    #pragma unroll
    for (int o = 16; o; o >>= 1) sum += __shfl_xor_sync(0xffffffffu, sum, o);
    float inv = 1.f / fmaxf(sqrtf(sum), EPSN);
    #pragma unroll
    for (int k = 0; k < 8; k++) dst[lane + 32 * k] = v[k] * inv;
}

// ---------------------------------------------------------------------------
// Kernel 2: fused dual-space scoring (R2 skeleton + 8-deep LDG prefetch).
// Block = 512 thr = 4 teams x 128. team = (space sp, channel-half ch).
// Each thread owns 2 adjacent columns; each team accumulates its space over
// its 128 channels. Video feats read exactly once from HBM. Mainloop uses a
// rolling 8-register prefetch so DRAM latency is overlapped per-warp.
// Partials combined via smem; team 0 runs the fused epilogue.
// grid = (16,16), block 512.
// ---------------------------------------------------------------------------
__global__ __launch_bounds__(TPB, 2) void score_kernel(
    const float* __restrict__ vf1,
    const float* __restrict__ vf2,
    const float* __restrict__ mask2d,
    float* __restrict__ out) {

    // 32 KB: phase A = duplicated sentence pairs, idx (spp*256+c)*8+s;
    // phase B = partial-sum scratch ((team-1)*128+ttid)*9 + k.
    __shared__ ull buf[4096];

    const int tid  = threadIdx.x;
    const int team = tid >> 7;       // 0..3
    const int ttid = tid & 127;
    const int sp   = team >> 1;      // feature space
    const int ch   = team & 1;       // channel half
    const int b    = blockIdx.y;
    const int ij0  = blockIdx.x * 256 + 2 * ttid;

    const int start = g_off[b];
    int end = g_off[b + 1];
    if (end > Ss) end = Ss;
    if (start >= end) return;        // uniform per block

    const float* vf = (sp == 0) ? vf1 : vf2;
    const ull* __restrict__ v = reinterpret_cast<const ull*>(
        vf + ((size_t)b * Cc + (size_t)ch * 128) * NN + ij0);

    const ull* __restrict__ sb = buf + (size_t)(sp * 256 + ch * 128) * 8;

    for (int cs = start; cs < end; cs += 8) {
        const int cnt = min(8, end - cs);

        // Phase A: stage duplicated sentence scalars (all 512 threads)
        for (int e = tid; e < 2 * Cc * 8; e += TPB) {
            const int s   = e & 7;
            const int c   = (e >> 3) & (Cc - 1);
            const int spp = e >> 11;
            float val = 0.f;
            if (s < cnt)
                val = (spp == 0 ? g_sn1 : g_sn2)[(size_t)(cs + s) * Cc + c];
            float2 d = make_float2(val, val);
            buf[e] = *reinterpret_cast<ull*>(&d);
        }
        __syncthreads();

        ull acc[8];
        #pragma unroll
        for (int s = 0; s < 8; s++) acc[s] = 0ull;
        ull nrm = 0ull;

        // ---- Mainloop with rolling 8-deep prefetch ----
        const ull* vp  = v;    // load pointer (channel g+8+i lives here)
        const ull* sbk = sb;   // sentence smem pointer for channel g+i

        ull pf[8];
        #pragma unroll
        for (int i = 0; i < 8; i++) pf[i] = vp[(size_t)i * (NN / 2)];

        #pragma unroll 1
        for (int g = 0; g < 120; g += 8) {
            #pragma unroll
            for (int i = 0; i < 8; i++) {
                const ull a = pf[i];
                pf[i] = vp[(size_t)(i + 8) * (NN / 2)];
                const ulonglong2* p =
                    reinterpret_cast<const ulonglong2*>(sbk + i * 8);
                FFMA2(nrm, a, a);
                const ulonglong2 q0 = p[0];
                const ulonglong2 q1 = p[1];
                FFMA2(acc[0], a, q0.x); FFMA2(acc[1], a, q0.y);
                FFMA2(acc[2], a, q1.x); FFMA2(acc[3], a, q1.y);
                const ulonglong2 q2 = p[2];
                const ulonglong2 q3 = p[3];
                FFMA2(acc[4], a, q2.x); FFMA2(acc[5], a, q2.y);
                FFMA2(acc[6], a, q3.x); FFMA2(acc[7], a, q3.y);
            }
            vp  += (size_t)8 * (NN / 2);
            sbk += 64;
        }
        // Drain: channels 120..127 already in pf
        #pragma unroll
        for (int i = 0; i < 8; i++) {
            const ull a = pf[i];
            const ulonglong2* p =
                reinterpret_cast<const ulonglong2*>(sbk + i * 8);
            FFMA2(nrm, a, a);
            const ulonglong2 q0 = p[0];
            const ulonglong2 q1 = p[1];
            FFMA2(acc[0], a, q0.x); FFMA2(acc[1], a, q0.y);
            FFMA2(acc[2], a, q1.x); FFMA2(acc[3], a, q1.y);
            const ulonglong2 q2 = p[2];
            const ulonglong2 q3 = p[3];
            FFMA2(acc[4], a, q2.x); FFMA2(acc[5], a, q2.y);
            FFMA2(acc[6], a, q3.x); FFMA2(acc[7], a, q3.y);
        }
        __syncthreads();   // done reading sentence smem

        // Phase B: teams 1..3 publish partials
        if (team != 0) {
            ull* r = buf + ((size_t)(team - 1) * 128 + ttid) * 9;
            #pragma unroll
            for (int s = 0; s < 8; s++) r[s] = acc[s];
            r[8] = nrm;
        }
        __syncthreads();

        if (team == 0) {
            const ull* r1 = buf + ((size_t)0 * 128 + ttid) * 9; // sp0, ch1
            const ull* r2 = buf + ((size_t)1 * 128 + ttid) * 9; // sp1, ch0
            const ull* r3 = buf + ((size_t)2 * 128 + ttid) * 9; // sp1, ch1

            ull t1[8], t2[8], n1, n2;
            #pragma unroll
            for (int s = 0; s < 8; s++) {
                FADD2(t1[s], acc[s], r1[s]);
                FADD2(t2[s], r2[s], r3[s]);
            }
            FADD2(n1, nrm, r1[8]);
            FADD2(n2, r2[8], r3[8]);

            const float i1lo = 1.f / fmaxf(sqrtf(f2lo(n1)), EPSN);
            const float i1hi = 1.f / fmaxf(sqrtf(f2hi(n1)), EPSN);
            const float i2lo = 1.f / fmaxf(sqrtf(f2lo(n2)), EPSN);
            const float i2hi = 1.f / fmaxf(sqrtf(f2hi(n2)), EPSN);

            const float2 mv = *reinterpret_cast<const float2*>(mask2d + ij0);
            const float m0 = mv.x, m1 = mv.y;

            for (int s = 0; s < cnt; s++) {
                const size_t srow = (size_t)(cs + s);
                const float lglo = SCALE * (f2lo(t1[s]) * i1lo);
                const float lghi = SCALE * (f2hi(t1[s]) * i1hi);
                *reinterpret_cast<float2*>(out + srow * NN + ij0) =
                    make_float2(lglo, lghi);

                const float ioulo = m0 / (1.f + __expf(-lglo));
                const float iouhi = m1 / (1.f + __expf(-lghi));
                const float conlo =
                    fmaxf((f2lo(t2[s]) * i2lo + 1.f) * 0.5f * m0, 0.f);
                const float conhi =
                    fmaxf((f2hi(t2[s]) * i2hi + 1.f) * 0.5f * m1, 0.f);
                *reinterpret_cast<float2*>(
                    out + (size_t)Ss * NN + srow * NN + ij0) =
                    make_float2(sqrtf(conlo) * ioulo, sqrtf(conhi) * iouhi);
            }
        }
        __syncthreads();   // buf safe to restage
    }
}

// ---------------------------------------------------------------------------
extern "C" void kernel_launch(void* const* d_in, const int* in_sizes, int n_in,
                              void* d_out, int out_size) {
    const float* vf1  = (const float*)d_in[0];
    const float* vf2  = (const float*)d_in[1];
    const float* sf1  = (const float*)d_in[2];
    const float* sf2  = (const float*)d_in[3];
    const float* mask = (const float*)d_in[4];
    const int*   nums = (const int*)d_in[5];
    float* out = (float*)d_out;

    prep_kernel<<<(2 * Ss) / 8, 256>>>(sf1, sf2, nums);
    score_kernel<<<dim3(NN / 256, Bv), TPB>>>(vf1, vf2, mask, out);
}

// round 8
// speedup vs baseline: 1.3479x; 1.0016x over previous
#include <cuda_runtime.h>
#include <math.h>

// Fixed problem shapes
#define Bv   16
#define Cc   256
#define Nn   64
#define NN   4096
#define Ss   128
#define EPSN 1e-12f
#define SCALE 10.0f
#define TPB  512     // 4 teams x 128 threads

typedef unsigned long long ull;

// Scratch: normalized sentence features + offsets
__device__ float g_sn1[Ss * Cc];
__device__ float g_sn2[Ss * Cc];
__device__ int   g_off[Bv + 1];

// Packed dual-fp32 FMA / ADD (Blackwell)
#define FFMA2(acc, a, bb) \
    asm("fma.rn.f32x2 %0, %1, %2, %0;" : "+l"(acc) : "l"(a), "l"(bb))
#define FADD2(dst, a, bb) \
    asm("add.rn.f32x2 %0, %1, %2;" : "=l"(dst) : "l"(a), "l"(bb))

__device__ __forceinline__ float f2lo(ull x) {
    return __uint_as_float((unsigned)(x & 0xffffffffu));
}
__device__ __forceinline__ float f2hi(ull x) {
    return __uint_as_float((unsigned)(x >> 32));
}
__device__ __forceinline__ ull dup32(unsigned x) {
    ull d;
    asm("mov.b64 %0, {%1, %1};" : "=l"(d) : "r"(x));
    return d;
}

// ---------------------------------------------------------------------------
// Kernel 1: normalize sentence features (warp per row) + prefix offsets
// ---------------------------------------------------------------------------
__global__ void prep_kernel(const float* __restrict__ sf1,
                            const float* __restrict__ sf2,
                            const int*   __restrict__ nums) {
    if (blockIdx.x == 0 && threadIdx.x == 0) {
        int acc = 0;
        g_off[0] = 0;
        #pragma unroll
        for (int i = 0; i < Bv; i++) { acc += nums[i]; g_off[i + 1] = acc; }
    }
    int warp = threadIdx.x >> 5;
    int lane = threadIdx.x & 31;
    int row  = blockIdx.x * 8 + warp;   // 2S rows
    const float* src;
    float* dst;
    if (row < Ss) { src = sf1 + (size_t)row * Cc;        dst = g_sn1 + (size_t)row * Cc; }
    else          { src = sf2 + (size_t)(row - Ss) * Cc; dst = g_sn2 + (size_t)(row - Ss) * Cc; }

    float v[8];
    float sum = 0.f;
    #pragma unroll
    for (int k = 0; k < 8; k++) {
        v[k] = src[lane + 32 * k];
        sum += v[k] * v[k];
    }
    #pragma unroll
    for (int o = 16; o; o >>= 1) sum += __shfl_xor_sync(0xffffffffu, sum, o);
    float inv = 1.f / fmaxf(sqrtf(sum), EPSN);
    #pragma unroll
    for (int k = 0; k < 8; k++) dst[lane + 32 * k] = v[k] * inv;
}

// ---------------------------------------------------------------------------
// Kernel 2: fused dual-space scoring, sentence-pair FFMA2 lanes.
// Block = 512 thr = 4 teams x 128. team = (space sp, channel-half ch).
// Thread owns 2 adjacent columns; FFMA2 lanes = (sent 2p, sent 2p+1), so
// smem holds sentence features UNduplicated (2 LDS.128/channel, half the
// L1tex wavefronts of the {v,v} layout). Video dup built with mov.b64.
// Video feats read exactly once from HBM; partials combined via smem;
// team 0 runs the fused epilogue. grid = (16,16), block 512.
// ---------------------------------------------------------------------------
__global__ __launch_bounds__(TPB, 2) void score_kernel(
    const float* __restrict__ vf1,
    const float* __restrict__ vf2,
    const float* __restrict__ mask2d,
    float* __restrict__ out) {

    // 27.6 KB, two phase-disjoint uses:
    //  - stage: sentence pairs, idx sp*1024 + c*4 + p   (2048 ull used)
    //  - reduce: 384 slots x 9 ull (max idx 3455)
    __shared__ __align__(16) ull buf[3456];

    const int tid  = threadIdx.x;
    const int team = tid >> 7;       // 0..3
    const int ttid = tid & 127;
    const int sp   = team >> 1;      // feature space
    const int ch   = team & 1;       // channel half
    const int b    = blockIdx.y;
    const int ij0  = blockIdx.x * 256 + 2 * ttid;

    const int start = g_off[b];
    int end = g_off[b + 1];
    if (end > Ss) end = Ss;
    if (start >= end) return;        // uniform per block

    const float* vf = (sp == 0) ? vf1 : vf2;
    const ull* __restrict__ v = reinterpret_cast<const ull*>(
        vf + ((size_t)b * Cc + (size_t)ch * 128) * NN + ij0);

    const ull* __restrict__ sb = buf + (size_t)sp * 1024 + (size_t)ch * 512;

    for (int cs = start; cs < end; cs += 8) {
        const int cnt = min(8, end - cs);

        // Stage sentence pairs {s2p, s2p+1} per (space, channel): 2048 ull
        for (int e = tid; e < 2048; e += TPB) {
            const int p   = e & 3;
            const int c   = (e >> 2) & (Cc - 1);
            const int spp = e >> 10;
            const float* g = spp ? g_sn2 : g_sn1;
            float x0 = 0.f, x1 = 0.f;
            if (2 * p < cnt)     x0 = g[(size_t)(cs + 2 * p) * Cc + c];
            if (2 * p + 1 < cnt) x1 = g[(size_t)(cs + 2 * p + 1) * Cc + c];
            float2 d = make_float2(x0, x1);
            buf[e] = *reinterpret_cast<ull*>(&d);
        }
        __syncthreads();

        // acc[p*2+c]: lanes = (sent 2p, sent 2p+1), c = column 0/1
        ull acc[8];
        #pragma unroll
        for (int s = 0; s < 8; s++) acc[s] = 0ull;
        ull nrm = 0ull;                 // lanes = (col0, col1)

        #pragma unroll 4
        for (int k = 0; k < 128; k++) {
            const ull a = v[(size_t)k * (NN / 2)];
            FFMA2(nrm, a, a);
            const unsigned a0 = (unsigned)a;
            const unsigned a1 = (unsigned)(a >> 32);
            const ull d0 = dup32(a0);
            const ull d1 = dup32(a1);
            const ulonglong2* p2 =
                reinterpret_cast<const ulonglong2*>(sb + k * 4);
            const ulonglong2 q0 = p2[0];   // {s0,s1},{s2,s3}
            FFMA2(acc[0], d0, q0.x); FFMA2(acc[1], d1, q0.x);
            FFMA2(acc[2], d0, q0.y); FFMA2(acc[3], d1, q0.y);
            const ulonglong2 q1 = p2[1];   // {s4,s5},{s6,s7}
            FFMA2(acc[4], d0, q1.x); FFMA2(acc[5], d1, q1.x);
            FFMA2(acc[6], d0, q1.y); FFMA2(acc[7], d1, q1.y);
        }
        __syncthreads();   // stage reads done; buf now reduction scratch

        // Teams 1..3 publish partials (9 ull each)
        if (team != 0) {
            ull* r = buf + ((size_t)(team - 1) * 128 + ttid) * 9;
            #pragma unroll
            for (int s = 0; s < 8; s++) r[s] = acc[s];
            r[8] = nrm;
        }
        __syncthreads();

        if (team == 0) {
            const ull* r1 = buf + ((size_t)0 * 128 + ttid) * 9; // sp0, ch1
            const ull* r2 = buf + ((size_t)1 * 128 + ttid) * 9; // sp1, ch0
            const ull* r3 = buf + ((size_t)2 * 128 + ttid) * 9; // sp1, ch1

            ull t1[8], t2[8], n1, n2;
            #pragma unroll
            for (int s = 0; s < 8; s++) {
                FADD2(t1[s], acc[s], r1[s]);
                FADD2(t2[s], r2[s], r3[s]);
            }
            FADD2(n1, nrm, r1[8]);
            FADD2(n2, r2[8], r3[8]);

            // n lanes = (col0, col1)
            const float i1c0 = 1.f / fmaxf(sqrtf(f2lo(n1)), EPSN);
            const float i1c1 = 1.f / fmaxf(sqrtf(f2hi(n1)), EPSN);
            const float i2c0 = 1.f / fmaxf(sqrtf(f2lo(n2)), EPSN);
            const float i2c1 = 1.f / fmaxf(sqrtf(f2hi(n2)), EPSN);

            const float2 mv = *reinterpret_cast<const float2*>(mask2d + ij0);
            const float m0 = mv.x, m1 = mv.y;

            for (int s = 0; s < cnt; s++) {
                const size_t srow = (size_t)(cs + s);
                const int p = s >> 1;
                const bool hi = (s & 1) != 0;
                const float d1c0 = hi ? f2hi(t1[p * 2 + 0]) : f2lo(t1[p * 2 + 0]);
                const float d1c1 = hi ? f2hi(t1[p * 2 + 1]) : f2lo(t1[p * 2 + 1]);
                const float d2c0 = hi ? f2hi(t2[p * 2 + 0]) : f2lo(t2[p * 2 + 0]);
                const float d2c1 = hi ? f2hi(t2[p * 2 + 1]) : f2lo(t2[p * 2 + 1]);

                const float lglo = SCALE * (d1c0 * i1c0);
                const float lghi = SCALE * (d1c1 * i1c1);
                *reinterpret_cast<float2*>(out + srow * NN + ij0) =
                    make_float2(lglo, lghi);

                const float ioulo = m0 / (1.f + __expf(-lglo));
                const float iouhi = m1 / (1.f + __expf(-lghi));
                const float conlo =
                    fmaxf((d2c0 * i2c0 + 1.f) * 0.5f * m0, 0.f);
                const float conhi =
                    fmaxf((d2c1 * i2c1 + 1.f) * 0.5f * m1, 0.f);
                *reinterpret_cast<float2*>(
                    out + (size_t)Ss * NN + srow * NN + ij0) =
                    make_float2(sqrtf(conlo) * ioulo, sqrtf(conhi) * iouhi);
            }
        }
        __syncthreads();   // buf safe to restage
    }
}

// ---------------------------------------------------------------------------
extern "C" void kernel_launch(void* const* d_in, const int* in_sizes, int n_in,
                              void* d_out, int out_size) {
    const float* vf1  = (const float*)d_in[0];
    const float* vf2  = (const float*)d_in[1];
    const float* sf1  = (const float*)d_in[2];
    const float* sf2  = (const float*)d_in[3];
    const float* mask = (const float*)d_in[4];
    const int*   nums = (const int*)d_in[5];
    float* out = (float*)d_out;

    prep_kernel<<<(2 * Ss) / 8, 256>>>(sf1, sf2, nums);
    score_kernel<<<dim3(NN / 256, Bv), TPB>>>(vf1, vf2, mask, out);
}